// round 10
// baseline (speedup 1.0000x reference)
#include <cuda_runtime.h>
#include <cuda_fp16.h>
#include <cstdint>

#define NB      2
#define H       48
#define W       48
#define HW      (H * W)          // 2304
#define DMODEL  768
#define DHEAD   64
#define NHEADS  12
#define M_TOT   (NB * HW)        // 4608
#define QKV_N   (3 * DMODEL)     // 2304

__device__ __half g_qkv16[(size_t)M_TOT * QKV_N]; // fp16: q|k|v
__device__ __half g_o16[(size_t)M_TOT * DMODEL];  // attention output, fp16
__device__ __half g_x16[(size_t)M_TOT * DMODEL];  // x, fp16
__device__ __half g_wq16[(size_t)QKV_N * DMODEL]; // w_qkv, fp16
__device__ __half g_wo16[(size_t)DMODEL * DMODEL];// w_out, fp16

__device__ __forceinline__ uint32_t h2_bits(__half2 h) {
    return *reinterpret_cast<uint32_t*>(&h);
}
__device__ __forceinline__ __half2 bits_h2(uint32_t u) {
    return *reinterpret_cast<__half2*>(&u);
}

__device__ __forceinline__ void mma_f16(
    float& d0, float& d1, float& d2, float& d3,
    uint32_t a0, uint32_t a1, uint32_t a2, uint32_t a3,
    uint32_t b0, uint32_t b1)
{
    asm volatile(
        "mma.sync.aligned.m16n8k16.row.col.f32.f16.f16.f32 "
        "{%0,%1,%2,%3}, {%4,%5,%6,%7}, {%8,%9}, {%0,%1,%2,%3};"
        : "+f"(d0), "+f"(d1), "+f"(d2), "+f"(d3)
        : "r"(a0), "r"(a1), "r"(a2), "r"(a3), "r"(b0), "r"(b1));
}

__device__ __forceinline__ void cp16(uint32_t saddr, const void* g) {
    asm volatile("cp.async.cg.shared.global [%0], [%1], 16;"
                 :: "r"(saddr), "l"(g));
}
__device__ __forceinline__ uint32_t s2u(const void* p) {
    return (uint32_t)__cvta_generic_to_shared(p);
}

// ---------------------------------------------------------------------------
// Elementwise fp32 -> fp16 pre-convert.
// ---------------------------------------------------------------------------
__global__ void cvt16_kernel(const float* __restrict__ src,
                             __half* __restrict__ dst, int n4)
{
    int i = blockIdx.x * blockDim.x + threadIdx.x;
    const int stride = gridDim.x * blockDim.x;
    for (; i < n4; i += stride) {
        float4 v = ((const float4*)src)[i];
        uint2 o;
        o.x = h2_bits(__floats2half2_rn(v.x, v.y));
        o.y = h2_bits(__floats2half2_rn(v.z, v.w));
        ((uint2*)dst)[i] = o;
    }
}

// ---------------------------------------------------------------------------
// FP16 GEMM (NT), 2-stage cp.async: C[m][n] = sum_k A[m][k]*B[n][k]
// BM=BN=128, BK=16, 256 threads, 8 warps (4x2), warp tile 32x64.
// out_half: write __half (QKV path); else fp32 (final output).
// ---------------------------------------------------------------------------
#define LDH 12
#define SW  (128 * LDH)

__global__ __launch_bounds__(256) void gemm_f16_async(
    const __half* __restrict__ A, const __half* __restrict__ B,
    void* __restrict__ Cv, int M, int N, int K, int out_half)
{
    extern __shared__ uint32_t sm[];
    uint32_t* Asm = sm;
    uint32_t* Bsm = sm + 2 * SW;

    const int tid  = threadIdx.x;
    const int lane = tid & 31;
    const int warp = tid >> 5;
    const int wm = (warp & 3) * 32;
    const int wn = (warp >> 2) * 64;
    const int rowBase = blockIdx.y * 128;
    const int colBase = blockIdx.x * 128;
    const int r = lane >> 2;
    const int q = lane & 3;

    float acc[2][8][4];
    #pragma unroll
    for (int i = 0; i < 2; i++)
        #pragma unroll
        for (int jn = 0; jn < 8; jn++)
            #pragma unroll
            for (int t = 0; t < 4; t++)
                acc[i][jn][t] = 0.0f;

    const int crow = tid >> 1;
    const int chalf = tid & 1;
    const __half* Ap = A + (size_t)(rowBase + crow) * K + chalf * 8;
    const __half* Bp = B + (size_t)(colBase + crow) * K + chalf * 8;

    uint32_t sA[2], sB[2];
    #pragma unroll
    for (int s = 0; s < 2; s++) {
        sA[s] = s2u(&Asm[s * SW + crow * LDH + chalf * 4]);
        sB[s] = s2u(&Bsm[s * SW + crow * LDH + chalf * 4]);
    }

    cp16(sA[0], Ap);
    cp16(sB[0], Bp);
    asm volatile("cp.async.commit_group;");

    const int T = K / 16;
    for (int t = 0; t < T; t++) {
        const int cur = t & 1;
        const int nxt = cur ^ 1;
        const bool more = (t + 1 < T);
        if (more) {
            const int k0 = (t + 1) * 16;
            cp16(sA[nxt], Ap + k0);
            cp16(sB[nxt], Bp + k0);
            asm volatile("cp.async.commit_group;");
            asm volatile("cp.async.wait_group 1;");
        } else {
            asm volatile("cp.async.wait_group 0;");
        }
        __syncthreads();

        const uint32_t* Ac = Asm + cur * SW;
        const uint32_t* Bc = Bsm + cur * SW;

        uint32_t af[2][4];
        #pragma unroll
        for (int i = 0; i < 2; i++) {
            const int rr = wm + i * 16 + r;
            af[i][0] = Ac[rr * LDH + q];
            af[i][1] = Ac[(rr + 8) * LDH + q];
            af[i][2] = Ac[rr * LDH + q + 4];
            af[i][3] = Ac[(rr + 8) * LDH + q + 4];
        }
        #pragma unroll
        for (int jn = 0; jn < 8; jn++) {
            const int cc = wn + jn * 8 + r;
            const uint32_t b0 = Bc[cc * LDH + q];
            const uint32_t b1 = Bc[cc * LDH + q + 4];
            #pragma unroll
            for (int i = 0; i < 2; i++)
                mma_f16(acc[i][jn][0], acc[i][jn][1], acc[i][jn][2], acc[i][jn][3],
                        af[i][0], af[i][1], af[i][2], af[i][3], b0, b1);
        }
        __syncthreads();
    }

    #pragma unroll
    for (int i = 0; i < 2; i++) {
        #pragma unroll
        for (int jn = 0; jn < 8; jn++) {
            const int row = rowBase + wm + i * 16 + r;
            const int col = colBase + wn + jn * 8 + q * 2;
            if (out_half) {
                __half* Ch = (__half*)Cv;
                *(uint32_t*)(Ch + (size_t)row * N + col) =
                    h2_bits(__floats2half2_rn(acc[i][jn][0], acc[i][jn][1]));
                *(uint32_t*)(Ch + (size_t)(row + 8) * N + col) =
                    h2_bits(__floats2half2_rn(acc[i][jn][2], acc[i][jn][3]));
            } else {
                float* Cf = (float*)Cv;
                *(float2*)(Cf + (size_t)row * N + col) =
                    make_float2(acc[i][jn][0], acc[i][jn][1]);
                *(float2*)(Cf + (size_t)(row + 8) * N + col) =
                    make_float2(acc[i][jn][2], acc[i][jn][3]);
            }
        }
    }
}

// ---------------------------------------------------------------------------
// FP16 tensor-core neighborhood attention.
// CTA = (qx, head, b), 96 threads = 3 warps; warp w owns query rows
// [w*16, w*16+16). Per key-row kx: S = Q.K^T (m16n8k16.f16), register mask,
// online softmax (fp32), P staged fp16, O += P.V (m16n8k16.f16).
// V stored transposed (Vt[dim][keypair], half2 = two adjacent keys).
// ---------------------------------------------------------------------------
#define QK2_LD 36   // words per 64-half Q/K row (32 + 4 pad): bank 4r+j
#define PV_LD  28   // words per P row / Vt row (24 + 4 pad)

__global__ __launch_bounds__(96) void natten_mma(const int* __restrict__ ks_ptr)
{
    __shared__ uint32_t Qs[48 * QK2_LD];  // 6912 B
    __shared__ uint32_t Ks[48 * QK2_LD];  // 6912 B
    __shared__ uint32_t Vt[64 * PV_LD];   // 7168 B
    __shared__ uint32_t Ps[48 * PV_LD];   // 5376 B

    const int ks   = *ks_ptr;
    const int tid  = threadIdx.x;
    const int lane = tid & 31;
    const int warp = tid >> 5;
    const int qx   = blockIdx.x;
    const int head = blockIdx.y;
    const int b    = blockIdx.z;

    const int r = lane >> 2;
    const int j = lane & 3;
    const int grow = warp * 16 + r;

    // Q row-block (48x64 halves), scale by 0.125 (exact in fp16).
    const __half* qbase = g_qkv16 + (size_t)(b * HW + qx * W) * QKV_N + head * DHEAD;
    const __half2 hscale = __float2half2_rn(0.125f);
    for (int i = tid; i < 48 * 8; i += 96) {
        const int row = i >> 3, ch = i & 7;
        uint4 v = *(const uint4*)(qbase + (size_t)row * QKV_N + ch * 8);
        v.x = h2_bits(__hmul2(bits_h2(v.x), hscale));
        v.y = h2_bits(__hmul2(bits_h2(v.y), hscale));
        v.z = h2_bits(__hmul2(bits_h2(v.z), hscale));
        v.w = h2_bits(__hmul2(bits_h2(v.w), hscale));
        *(uint4*)&Qs[row * QK2_LD + ch * 4] = v;
    }

    float o[8][4];
    #pragma unroll
    for (int nt = 0; nt < 8; nt++)
        #pragma unroll
        for (int t = 0; t < 4; t++)
            o[nt][t] = 0.0f;
    float m0 = -1e30f, m1 = -1e30f, l0 = 0.0f, l1 = 0.0f;

    const int x0 = max(0, qx - ks), x1 = min(H - 1, qx + ks);

    for (int kx = x0; kx <= x1; kx++) {
        __syncthreads();   // previous iteration's MMA reads done
        const __half* krow = g_qkv16 + (size_t)(b * HW + kx * W) * QKV_N
                           + DMODEL + head * DHEAD;
        const __half* vrow = krow + DMODEL;

        // K: raw copy (48 keys x 8 uint4 chunks)
        for (int i = tid; i < 48 * 8; i += 96) {
            const int key = i >> 3, ch = i & 7;
            *(uint4*)&Ks[key * QK2_LD + ch * 4] =
                *(const uint4*)(krow + (size_t)key * QKV_N + ch * 8);
        }
        // V: transpose-pack (24 keypairs x 8 dim-groups)
        for (int t = tid; t < 24 * 8; t += 96) {
            const int kp = t >> 3, dg = t & 7;
            uint4 a  = *(const uint4*)(vrow + (size_t)(2 * kp)     * QKV_N + dg * 8);
            uint4 bq = *(const uint4*)(vrow + (size_t)(2 * kp + 1) * QKV_N + dg * 8);
            const uint32_t aw[4] = {a.x, a.y, a.z, a.w};
            const uint32_t bw[4] = {bq.x, bq.y, bq.z, bq.w};
            #pragma unroll
            for (int i = 0; i < 4; i++) {
                const int d = dg * 8 + 2 * i;
                Vt[d * PV_LD + kp]       = __byte_perm(aw[i], bw[i], 0x5410);
                Vt[(d + 1) * PV_LD + kp] = __byte_perm(aw[i], bw[i], 0x7632);
            }
        }
        __syncthreads();

        // ---- S = Q . K^T : 16x48 per warp (fp16 k16) ----
        float sc[6][4];
        #pragma unroll
        for (int nt = 0; nt < 6; nt++)
            #pragma unroll
            for (int t = 0; t < 4; t++)
                sc[nt][t] = 0.0f;

        #pragma unroll
        for (int kk = 0; kk < 4; kk++) {
            const uint32_t a0 = Qs[(warp * 16 + r)     * QK2_LD + kk * 8 + j];
            const uint32_t a1 = Qs[(warp * 16 + r + 8) * QK2_LD + kk * 8 + j];
            const uint32_t a2 = Qs[(warp * 16 + r)     * QK2_LD + kk * 8 + j + 4];
            const uint32_t a3 = Qs[(warp * 16 + r + 8) * QK2_LD + kk * 8 + j + 4];
            #pragma unroll
            for (int nt = 0; nt < 6; nt++) {
                const uint32_t b0 = Ks[(nt * 8 + r) * QK2_LD + kk * 8 + j];
                const uint32_t b1 = Ks[(nt * 8 + r) * QK2_LD + kk * 8 + j + 4];
                mma_f16(sc[nt][0], sc[nt][1], sc[nt][2], sc[nt][3],
                        a0, a1, a2, a3, b0, b1);
            }
        }

        // ---- mask + online softmax ----
        float rmax0 = -1e30f, rmax1 = -1e30f;
        #pragma unroll
        for (int nt = 0; nt < 6; nt++) {
            const int ky0 = nt * 8 + 2 * j;
            const int ky1 = ky0 + 1;
            if (abs(grow - ky0) > ks)     sc[nt][0] = -1e30f;
            if (abs(grow - ky1) > ks)     sc[nt][1] = -1e30f;
            if (abs(grow + 8 - ky0) > ks) sc[nt][2] = -1e30f;
            if (abs(grow + 8 - ky1) > ks) sc[nt][3] = -1e30f;
            rmax0 = fmaxf(rmax0, fmaxf(sc[nt][0], sc[nt][1]));
            rmax1 = fmaxf(rmax1, fmaxf(sc[nt][2], sc[nt][3]));
        }
        rmax0 = fmaxf(rmax0, __shfl_xor_sync(0xffffffffu, rmax0, 1));
        rmax0 = fmaxf(rmax0, __shfl_xor_sync(0xffffffffu, rmax0, 2));
        rmax1 = fmaxf(rmax1, __shfl_xor_sync(0xffffffffu, rmax1, 1));
        rmax1 = fmaxf(rmax1, __shfl_xor_sync(0xffffffffu, rmax1, 2));

        const float mn0 = fmaxf(m0, rmax0);
        const float mn1 = fmaxf(m1, rmax1);
        const float cr0 = __expf(m0 - mn0);
        const float cr1 = __expf(m1 - mn1);
        m0 = mn0; m1 = mn1;

        float ps0 = 0.0f, ps1 = 0.0f;
        #pragma unroll
        for (int nt = 0; nt < 6; nt++) {
            sc[nt][0] = __expf(sc[nt][0] - mn0);
            sc[nt][1] = __expf(sc[nt][1] - mn0);
            sc[nt][2] = __expf(sc[nt][2] - mn1);
            sc[nt][3] = __expf(sc[nt][3] - mn1);
            ps0 += sc[nt][0] + sc[nt][1];
            ps1 += sc[nt][2] + sc[nt][3];
        }
        ps0 += __shfl_xor_sync(0xffffffffu, ps0, 1);
        ps0 += __shfl_xor_sync(0xffffffffu, ps0, 2);
        ps1 += __shfl_xor_sync(0xffffffffu, ps1, 1);
        ps1 += __shfl_xor_sync(0xffffffffu, ps1, 2);
        l0 = l0 * cr0 + ps0;
        l1 = l1 * cr1 + ps1;

        #pragma unroll
        for (int nt = 0; nt < 8; nt++) {
            o[nt][0] *= cr0; o[nt][1] *= cr0;
            o[nt][2] *= cr1; o[nt][3] *= cr1;
        }

        // ---- stage P (fp16 pairs) ----
        #pragma unroll
        for (int nt = 0; nt < 6; nt++) {
            Ps[(grow)     * PV_LD + nt * 4 + j] =
                h2_bits(__floats2half2_rn(sc[nt][0], sc[nt][1]));
            Ps[(grow + 8) * PV_LD + nt * 4 + j] =
                h2_bits(__floats2half2_rn(sc[nt][2], sc[nt][3]));
        }
        __syncwarp();   // P tile is warp-private (own 16 rows)

        // ---- O += P . V : 16x64 per warp (fp16 k16, V^T layout) ----
        #pragma unroll
        for (int kk = 0; kk < 3; kk++) {
            const uint32_t a0 = Ps[(warp * 16 + r)     * PV_LD + kk * 8 + j];
            const uint32_t a1 = Ps[(warp * 16 + r + 8) * PV_LD + kk * 8 + j];
            const uint32_t a2 = Ps[(warp * 16 + r)     * PV_LD + kk * 8 + j + 4];
            const uint32_t a3 = Ps[(warp * 16 + r + 8) * PV_LD + kk * 8 + j + 4];
            #pragma unroll
            for (int nt = 0; nt < 8; nt++) {
                const uint32_t b0 = Vt[(nt * 8 + r) * PV_LD + kk * 8 + j];
                const uint32_t b1 = Vt[(nt * 8 + r) * PV_LD + kk * 8 + j + 4];
                mma_f16(o[nt][0], o[nt][1], o[nt][2], o[nt][3],
                        a0, a1, a2, a3, b0, b1);
            }
        }
    }

    // ---- writeout: fp16 for the fp16 out-projection ----
    const float inv0 = 1.0f / l0;
    const float inv1 = 1.0f / l1;
    __half* ob0 = g_o16 + (size_t)(b * HW + qx * W + grow)     * DMODEL + head * DHEAD;
    __half* ob1 = g_o16 + (size_t)(b * HW + qx * W + grow + 8) * DMODEL + head * DHEAD;
    #pragma unroll
    for (int nt = 0; nt < 8; nt++) {
        const int col = nt * 8 + 2 * j;
        *(uint32_t*)(ob0 + col) =
            h2_bits(__floats2half2_rn(o[nt][0] * inv0, o[nt][1] * inv0));
        *(uint32_t*)(ob1 + col) =
            h2_bits(__floats2half2_rn(o[nt][2] * inv1, o[nt][3] * inv1));
    }
}

// ---------------------------------------------------------------------------
extern "C" void kernel_launch(void* const* d_in, const int* in_sizes, int n_in,
                              void* d_out, int out_size)
{
    const float* x      = (const float*)d_in[0];
    const float* w_qkv  = (const float*)d_in[1];
    const float* w_out  = (const float*)d_in[2];
    const int*   ksp    = (const int*)  d_in[3];
    float*       out    = (float*)d_out;

    __half *qkv16_ptr, *o16_ptr, *x16_ptr, *wq16_ptr, *wo16_ptr;
    cudaGetSymbolAddress((void**)&qkv16_ptr, g_qkv16);
    cudaGetSymbolAddress((void**)&o16_ptr,   g_o16);
    cudaGetSymbolAddress((void**)&x16_ptr,   g_x16);
    cudaGetSymbolAddress((void**)&wq16_ptr,  g_wq16);
    cudaGetSymbolAddress((void**)&wo16_ptr,  g_wo16);

    const int GEMM_SMEM = 4 * SW * 4;   // 49152 B
    static int attr_set = 0;
    if (!attr_set) {
        cudaFuncSetAttribute(gemm_f16_async,
                             cudaFuncAttributeMaxDynamicSharedMemorySize, GEMM_SMEM);
        attr_set = 1;
    }

    // 0) fp16 pre-conversion of inputs
    cvt16_kernel<<<512, 256>>>(x,     x16_ptr,  M_TOT * DMODEL / 4);
    cvt16_kernel<<<512, 256>>>(w_qkv, wq16_ptr, QKV_N * DMODEL / 4);
    cvt16_kernel<<<256, 256>>>(w_out, wo16_ptr, DMODEL * DMODEL / 4);

    // 1) QKV projection (fp16 in, fp16 out)
    {
        dim3 grid(QKV_N / 128, M_TOT / 128);
        gemm_f16_async<<<grid, 256, GEMM_SMEM>>>(x16_ptr, wq16_ptr, qkv16_ptr,
                                                 M_TOT, QKV_N, DMODEL, 1);
    }

    // 2) FP16 tensor-core neighborhood attention
    {
        dim3 grid(H, NHEADS, NB);
        natten_mma<<<grid, 96>>>(ksp);
    }

    // 3) Output projection (fp16 in, fp32 out)
    {
        dim3 grid(DMODEL / 128, M_TOT / 128);
        gemm_f16_async<<<grid, 256, GEMM_SMEM>>>(o16_ptr, wo16_ptr, out,
                                                 M_TOT, DMODEL, DMODEL, 0);
    }
}

// round 11
// speedup vs baseline: 1.3134x; 1.3134x over previous
#include <cuda_runtime.h>
#include <cuda_fp16.h>
#include <cstdint>

#define NB      2
#define H       48
#define W       48
#define HW      (H * W)          // 2304
#define DMODEL  768
#define DHEAD   64
#define NHEADS  12
#define M_TOT   (NB * HW)        // 4608
#define QKV_N   (3 * DMODEL)     // 2304

__device__ __half g_qkv16[(size_t)M_TOT * QKV_N]; // fp16: q|k|v
__device__ __half g_o16[(size_t)M_TOT * DMODEL];  // attention output, fp16
__device__ __half g_x16[(size_t)M_TOT * DMODEL];  // x, fp16
__device__ __half g_wq16[(size_t)QKV_N * DMODEL]; // w_qkv, fp16
__device__ __half g_wo16[(size_t)DMODEL * DMODEL];// w_out, fp16

__device__ __forceinline__ uint32_t h2_bits(__half2 h) {
    return *reinterpret_cast<uint32_t*>(&h);
}
__device__ __forceinline__ __half2 bits_h2(uint32_t u) {
    return *reinterpret_cast<__half2*>(&u);
}

__device__ __forceinline__ void mma_f16(
    float& d0, float& d1, float& d2, float& d3,
    uint32_t a0, uint32_t a1, uint32_t a2, uint32_t a3,
    uint32_t b0, uint32_t b1)
{
    asm volatile(
        "mma.sync.aligned.m16n8k16.row.col.f32.f16.f16.f32 "
        "{%0,%1,%2,%3}, {%4,%5,%6,%7}, {%8,%9}, {%0,%1,%2,%3};"
        : "+f"(d0), "+f"(d1), "+f"(d2), "+f"(d3)
        : "r"(a0), "r"(a1), "r"(a2), "r"(a3), "r"(b0), "r"(b1));
}

__device__ __forceinline__ void ldsm4(
    uint32_t& r0, uint32_t& r1, uint32_t& r2, uint32_t& r3, uint32_t saddr)
{
    asm volatile("ldmatrix.sync.aligned.m8n8.x4.shared.b16 {%0,%1,%2,%3}, [%4];"
                 : "=r"(r0), "=r"(r1), "=r"(r2), "=r"(r3) : "r"(saddr));
}
__device__ __forceinline__ void ldsm4t(
    uint32_t& r0, uint32_t& r1, uint32_t& r2, uint32_t& r3, uint32_t saddr)
{
    asm volatile("ldmatrix.sync.aligned.m8n8.x4.trans.shared.b16 {%0,%1,%2,%3}, [%4];"
                 : "=r"(r0), "=r"(r1), "=r"(r2), "=r"(r3) : "r"(saddr));
}

__device__ __forceinline__ void cp16(uint32_t saddr, const void* g) {
    asm volatile("cp.async.cg.shared.global [%0], [%1], 16;"
                 :: "r"(saddr), "l"(g));
}
__device__ __forceinline__ uint32_t s2u(const void* p) {
    return (uint32_t)__cvta_generic_to_shared(p);
}

// ---------------------------------------------------------------------------
// Elementwise fp32 -> fp16 pre-convert.
// ---------------------------------------------------------------------------
__global__ void cvt16_kernel(const float* __restrict__ src,
                             __half* __restrict__ dst, int n4)
{
    int i = blockIdx.x * blockDim.x + threadIdx.x;
    const int stride = gridDim.x * blockDim.x;
    for (; i < n4; i += stride) {
        float4 v = ((const float4*)src)[i];
        uint2 o;
        o.x = h2_bits(__floats2half2_rn(v.x, v.y));
        o.y = h2_bits(__floats2half2_rn(v.z, v.w));
        ((uint2*)dst)[i] = o;
    }
}

// ---------------------------------------------------------------------------
// FP16 GEMM (NT), 2-stage cp.async (unchanged — validated R9/R10).
// ---------------------------------------------------------------------------
#define LDH 12
#define SW  (128 * LDH)

__global__ __launch_bounds__(256) void gemm_f16_async(
    const __half* __restrict__ A, const __half* __restrict__ B,
    void* __restrict__ Cv, int M, int N, int K, int out_half)
{
    extern __shared__ uint32_t sm[];
    uint32_t* Asm = sm;
    uint32_t* Bsm = sm + 2 * SW;

    const int tid  = threadIdx.x;
    const int lane = tid & 31;
    const int warp = tid >> 5;
    const int wm = (warp & 3) * 32;
    const int wn = (warp >> 2) * 64;
    const int rowBase = blockIdx.y * 128;
    const int colBase = blockIdx.x * 128;
    const int r = lane >> 2;
    const int q = lane & 3;

    float acc[2][8][4];
    #pragma unroll
    for (int i = 0; i < 2; i++)
        #pragma unroll
        for (int jn = 0; jn < 8; jn++)
            #pragma unroll
            for (int t = 0; t < 4; t++)
                acc[i][jn][t] = 0.0f;

    const int crow = tid >> 1;
    const int chalf = tid & 1;
    const __half* Ap = A + (size_t)(rowBase + crow) * K + chalf * 8;
    const __half* Bp = B + (size_t)(colBase + crow) * K + chalf * 8;

    uint32_t sA[2], sB[2];
    #pragma unroll
    for (int s = 0; s < 2; s++) {
        sA[s] = s2u(&Asm[s * SW + crow * LDH + chalf * 4]);
        sB[s] = s2u(&Bsm[s * SW + crow * LDH + chalf * 4]);
    }

    cp16(sA[0], Ap);
    cp16(sB[0], Bp);
    asm volatile("cp.async.commit_group;");

    const int T = K / 16;
    for (int t = 0; t < T; t++) {
        const int cur = t & 1;
        const int nxt = cur ^ 1;
        const bool more = (t + 1 < T);
        if (more) {
            const int k0 = (t + 1) * 16;
            cp16(sA[nxt], Ap + k0);
            cp16(sB[nxt], Bp + k0);
            asm volatile("cp.async.commit_group;");
            asm volatile("cp.async.wait_group 1;");
        } else {
            asm volatile("cp.async.wait_group 0;");
        }
        __syncthreads();

        const uint32_t* Ac = Asm + cur * SW;
        const uint32_t* Bc = Bsm + cur * SW;

        uint32_t af[2][4];
        #pragma unroll
        for (int i = 0; i < 2; i++) {
            const int rr = wm + i * 16 + r;
            af[i][0] = Ac[rr * LDH + q];
            af[i][1] = Ac[(rr + 8) * LDH + q];
            af[i][2] = Ac[rr * LDH + q + 4];
            af[i][3] = Ac[(rr + 8) * LDH + q + 4];
        }
        #pragma unroll
        for (int jn = 0; jn < 8; jn++) {
            const int cc = wn + jn * 8 + r;
            const uint32_t b0 = Bc[cc * LDH + q];
            const uint32_t b1 = Bc[cc * LDH + q + 4];
            #pragma unroll
            for (int i = 0; i < 2; i++)
                mma_f16(acc[i][jn][0], acc[i][jn][1], acc[i][jn][2], acc[i][jn][3],
                        af[i][0], af[i][1], af[i][2], af[i][3], b0, b1);
        }
        __syncthreads();
    }

    #pragma unroll
    for (int i = 0; i < 2; i++) {
        #pragma unroll
        for (int jn = 0; jn < 8; jn++) {
            const int row = rowBase + wm + i * 16 + r;
            const int col = colBase + wn + jn * 8 + q * 2;
            if (out_half) {
                __half* Ch = (__half*)Cv;
                *(uint32_t*)(Ch + (size_t)row * N + col) =
                    h2_bits(__floats2half2_rn(acc[i][jn][0], acc[i][jn][1]));
                *(uint32_t*)(Ch + (size_t)(row + 8) * N + col) =
                    h2_bits(__floats2half2_rn(acc[i][jn][2], acc[i][jn][3]));
            } else {
                float* Cf = (float*)Cv;
                *(float2*)(Cf + (size_t)row * N + col) =
                    make_float2(acc[i][jn][0], acc[i][jn][1]);
                *(float2*)(Cf + (size_t)(row + 8) * N + col) =
                    make_float2(acc[i][jn][2], acc[i][jn][3]);
            }
        }
    }
}

// ---------------------------------------------------------------------------
// FP16 tensor-core neighborhood attention, v2:
//   - ldmatrix for Q (hoisted), K (x4), V (x4.trans on RAW rows; no transpose)
//   - P passed register-to-register (S-accum layout == fp16 A-frag layout)
//   - 3-stage cp.async pipeline over key-rows, 1 __syncthreads per kx
// CTA = (qx, head, b), 96 threads = 3 warps; warp w owns query rows
// [w*16, w*16+16). Rows stored at 144 B stride (64 halves + 8 pad):
// ldmatrix row-bank = 4*row mod 32 -> conflict-free.
// smem = 7 * 6912 B = 48384 B (static).
// ---------------------------------------------------------------------------
#define RLD 36   // words per row (64 halves + 8 pad)
#define RB  144  // bytes per row
#define TWORDS (48 * RLD)

__global__ __launch_bounds__(96) void natten_mma(const int* __restrict__ ks_ptr)
{
    __shared__ __align__(16) uint32_t Qs[TWORDS];
    __shared__ __align__(16) uint32_t Kb[3][TWORDS];
    __shared__ __align__(16) uint32_t Vb[3][TWORDS];

    const int ks   = *ks_ptr;
    const int tid  = threadIdx.x;
    const int lane = tid & 31;
    const int warp = tid >> 5;
    const int qx   = blockIdx.x;
    const int head = blockIdx.y;
    const int b    = blockIdx.z;

    const int r = lane >> 2;          // 0..7
    const int j = lane & 3;           // 0..3
    const int grow = warp * 16 + r;   // query y for c0/c1 (grow+8 for c2/c3)

    // ldmatrix per-lane row/col offset (same formula for Q, K, V addressing)
    const uint32_t lmoff = (uint32_t)((lane & 15) * RB + (lane >> 4) * 16);

    // ---- Q: load, scale by 0.125 (exact), store to smem ----
    const __half* qbase = g_qkv16 + (size_t)(b * HW + qx * W) * QKV_N + head * DHEAD;
    const __half2 hscale = __float2half2_rn(0.125f);
    for (int i = tid; i < 48 * 8; i += 96) {
        const int row = i >> 3, ch = i & 7;
        uint4 v = *(const uint4*)(qbase + (size_t)row * QKV_N + ch * 8);
        v.x = h2_bits(__hmul2(bits_h2(v.x), hscale));
        v.y = h2_bits(__hmul2(bits_h2(v.y), hscale));
        v.z = h2_bits(__hmul2(bits_h2(v.z), hscale));
        v.w = h2_bits(__hmul2(bits_h2(v.w), hscale));
        *(uint4*)&Qs[row * RLD + ch * 4] = v;
    }

    const int x0 = max(0, qx - ks), x1 = min(H - 1, qx + ks);
    const int nkx = x1 - x0 + 1;   // 8..15

    const __half* kvbase = g_qkv16 + (size_t)(b * HW) * QKV_N + DMODEL + head * DHEAD;

    uint32_t kS[3], vS[3];
    #pragma unroll
    for (int s = 0; s < 3; s++) {
        kS[s] = s2u(&Kb[s][0]);
        vS[s] = s2u(&Vb[s][0]);
    }

    // cp.async fill of one key-row tile (K 6KB + V 6KB): 8 chunks/thread
    auto fill = [&](int buf, int kx) {
        const __half* krow = kvbase + (size_t)(kx * W) * QKV_N;
        const __half* vrow = krow + DMODEL;
        #pragma unroll
        for (int c = 0; c < 4; c++) {
            const int chunk = tid + c * 96;
            const int row = chunk >> 3, ch = chunk & 7;
            const size_t goff = (size_t)row * QKV_N + ch * 8;
            const uint32_t soff = (uint32_t)(row * RB + ch * 16);
            cp16(kS[buf] + soff, krow + goff);
            cp16(vS[buf] + soff, vrow + goff);
        }
    };

    // Prologue: prefetch tiles 0 and 1
    fill(0, x0);
    asm volatile("cp.async.commit_group;");
    if (nkx > 1) fill(1, x0 + 1);
    asm volatile("cp.async.commit_group;");

    float o[8][4];
    #pragma unroll
    for (int nt = 0; nt < 8; nt++)
        #pragma unroll
        for (int t = 0; t < 4; t++)
            o[nt][t] = 0.0f;
    float m0 = -1e30f, m1 = -1e30f, l0 = 0.0f, l1 = 0.0f;

    // Q fragments, hoisted (loaded after first barrier below)
    uint32_t qf[4][4];
    bool qf_loaded = false;

    for (int t = 0; t < nkx; t++) {
        asm volatile("cp.async.wait_group 1;");
        __syncthreads();   // tile t visible to all; buf (t+2)%3 free to refill

        if (!qf_loaded) {
            const uint32_t qa = s2u(Qs) + (uint32_t)(warp * 16 * RB) + lmoff;
            #pragma unroll
            for (int kk = 0; kk < 4; kk++)
                ldsm4(qf[kk][0], qf[kk][1], qf[kk][2], qf[kk][3], qa + kk * 32);
            qf_loaded = true;
        }

        if (t + 2 < nkx) fill((t + 2) % 3, x0 + t + 2);
        asm volatile("cp.async.commit_group;");   // possibly empty; keeps counts

        const int buf = t % 3;

        // ---- S = Q . K^T : 16x48 per warp ----
        float sc[6][4];
        #pragma unroll
        for (int nt = 0; nt < 6; nt++)
            #pragma unroll
            for (int tt = 0; tt < 4; tt++)
                sc[nt][tt] = 0.0f;

        #pragma unroll
        for (int p = 0; p < 3; p++) {           // key 16-blocks
            const uint32_t ka = kS[buf] + (uint32_t)(16 * p * RB) + lmoff;
            #pragma unroll
            for (int kk = 0; kk < 4; kk++) {    // dim 16-blocks
                uint32_t b0a, b0b, b1a, b1b;
                ldsm4(b0a, b0b, b1a, b1b, ka + kk * 32);
                mma_f16(sc[2*p][0], sc[2*p][1], sc[2*p][2], sc[2*p][3],
                        qf[kk][0], qf[kk][1], qf[kk][2], qf[kk][3], b0a, b1a);
                mma_f16(sc[2*p+1][0], sc[2*p+1][1], sc[2*p+1][2], sc[2*p+1][3],
                        qf[kk][0], qf[kk][1], qf[kk][2], qf[kk][3], b0b, b1b);
            }
        }

        // ---- mask + online softmax ----
        float rmax0 = -1e30f, rmax1 = -1e30f;
        #pragma unroll
        for (int nt = 0; nt < 6; nt++) {
            const int ky0 = nt * 8 + 2 * j;
            const int ky1 = ky0 + 1;
            if (abs(grow - ky0) > ks)     sc[nt][0] = -1e30f;
            if (abs(grow - ky1) > ks)     sc[nt][1] = -1e30f;
            if (abs(grow + 8 - ky0) > ks) sc[nt][2] = -1e30f;
            if (abs(grow + 8 - ky1) > ks) sc[nt][3] = -1e30f;
            rmax0 = fmaxf(rmax0, fmaxf(sc[nt][0], sc[nt][1]));
            rmax1 = fmaxf(rmax1, fmaxf(sc[nt][2], sc[nt][3]));
        }
        rmax0 = fmaxf(rmax0, __shfl_xor_sync(0xffffffffu, rmax0, 1));
        rmax0 = fmaxf(rmax0, __shfl_xor_sync(0xffffffffu, rmax0, 2));
        rmax1 = fmaxf(rmax1, __shfl_xor_sync(0xffffffffu, rmax1, 1));
        rmax1 = fmaxf(rmax1, __shfl_xor_sync(0xffffffffu, rmax1, 2));

        const float mn0 = fmaxf(m0, rmax0);
        const float mn1 = fmaxf(m1, rmax1);
        const float cr0 = __expf(m0 - mn0);
        const float cr1 = __expf(m1 - mn1);
        m0 = mn0; m1 = mn1;

        float ps0 = 0.0f, ps1 = 0.0f;
        #pragma unroll
        for (int nt = 0; nt < 6; nt++) {
            sc[nt][0] = __expf(sc[nt][0] - mn0);
            sc[nt][1] = __expf(sc[nt][1] - mn0);
            sc[nt][2] = __expf(sc[nt][2] - mn1);
            sc[nt][3] = __expf(sc[nt][3] - mn1);
            ps0 += sc[nt][0] + sc[nt][1];
            ps1 += sc[nt][2] + sc[nt][3];
        }
        ps0 += __shfl_xor_sync(0xffffffffu, ps0, 1);
        ps0 += __shfl_xor_sync(0xffffffffu, ps0, 2);
        ps1 += __shfl_xor_sync(0xffffffffu, ps1, 1);
        ps1 += __shfl_xor_sync(0xffffffffu, ps1, 2);
        l0 = l0 * cr0 + ps0;
        l1 = l1 * cr1 + ps1;

        #pragma unroll
        for (int nt = 0; nt < 8; nt++) {
            o[nt][0] *= cr0; o[nt][1] *= cr0;
            o[nt][2] *= cr1; o[nt][3] *= cr1;
        }

        // ---- O += P . V : P direct from registers, V via ldmatrix.trans ----
        #pragma unroll
        for (int kk = 0; kk < 3; kk++) {        // key 16-blocks
            const uint32_t pa0 = h2_bits(__floats2half2_rn(sc[2*kk][0],   sc[2*kk][1]));
            const uint32_t pa1 = h2_bits(__floats2half2_rn(sc[2*kk][2],   sc[2*kk][3]));
            const uint32_t pa2 = h2_bits(__floats2half2_rn(sc[2*kk+1][0], sc[2*kk+1][1]));
            const uint32_t pa3 = h2_bits(__floats2half2_rn(sc[2*kk+1][2], sc[2*kk+1][3]));
            const uint32_t va = vS[buf] + (uint32_t)(16 * kk * RB) + lmoff;
            #pragma unroll
            for (int p = 0; p < 4; p++) {       // dim 16-blocks (2 n-tiles each)
                uint32_t b0a, b1a, b0b, b1b;
                ldsm4t(b0a, b1a, b0b, b1b, va + p * 32);
                mma_f16(o[2*p][0], o[2*p][1], o[2*p][2], o[2*p][3],
                        pa0, pa1, pa2, pa3, b0a, b1a);
                mma_f16(o[2*p+1][0], o[2*p+1][1], o[2*p+1][2], o[2*p+1][3],
                        pa0, pa1, pa2, pa3, b0b, b1b);
            }
        }
    }

    // ---- writeout: fp16 for the fp16 out-projection ----
    const float inv0 = 1.0f / l0;
    const float inv1 = 1.0f / l1;
    __half* ob0 = g_o16 + (size_t)(b * HW + qx * W + grow)     * DMODEL + head * DHEAD;
    __half* ob1 = g_o16 + (size_t)(b * HW + qx * W + grow + 8) * DMODEL + head * DHEAD;
    #pragma unroll
    for (int nt = 0; nt < 8; nt++) {
        const int col = nt * 8 + 2 * j;
        *(uint32_t*)(ob0 + col) =
            h2_bits(__floats2half2_rn(o[nt][0] * inv0, o[nt][1] * inv0));
        *(uint32_t*)(ob1 + col) =
            h2_bits(__floats2half2_rn(o[nt][2] * inv1, o[nt][3] * inv1));
    }
}

// ---------------------------------------------------------------------------
extern "C" void kernel_launch(void* const* d_in, const int* in_sizes, int n_in,
                              void* d_out, int out_size)
{
    const float* x      = (const float*)d_in[0];
    const float* w_qkv  = (const float*)d_in[1];
    const float* w_out  = (const float*)d_in[2];
    const int*   ksp    = (const int*)  d_in[3];
    float*       out    = (float*)d_out;

    __half *qkv16_ptr, *o16_ptr, *x16_ptr, *wq16_ptr, *wo16_ptr;
    cudaGetSymbolAddress((void**)&qkv16_ptr, g_qkv16);
    cudaGetSymbolAddress((void**)&o16_ptr,   g_o16);
    cudaGetSymbolAddress((void**)&x16_ptr,   g_x16);
    cudaGetSymbolAddress((void**)&wq16_ptr,  g_wq16);
    cudaGetSymbolAddress((void**)&wo16_ptr,  g_wo16);

    const int GEMM_SMEM = 4 * SW * 4;   // 49152 B
    static int attr_set = 0;
    if (!attr_set) {
        cudaFuncSetAttribute(gemm_f16_async,
                             cudaFuncAttributeMaxDynamicSharedMemorySize, GEMM_SMEM);
        attr_set = 1;
    }

    // 0) fp16 pre-conversion of inputs
    cvt16_kernel<<<512, 256>>>(x,     x16_ptr,  M_TOT * DMODEL / 4);
    cvt16_kernel<<<512, 256>>>(w_qkv, wq16_ptr, QKV_N * DMODEL / 4);
    cvt16_kernel<<<256, 256>>>(w_out, wo16_ptr, DMODEL * DMODEL / 4);

    // 1) QKV projection (fp16 in, fp16 out)
    {
        dim3 grid(QKV_N / 128, M_TOT / 128);
        gemm_f16_async<<<grid, 256, GEMM_SMEM>>>(x16_ptr, wq16_ptr, qkv16_ptr,
                                                 M_TOT, QKV_N, DMODEL, 1);
    }

    // 2) FP16 tensor-core neighborhood attention (ldmatrix + cp.async pipeline)
    {
        dim3 grid(H, NHEADS, NB);
        natten_mma<<<grid, 96>>>(ksp);
    }

    // 3) Output projection (fp16 in, fp32 out)
    {
        dim3 grid(DMODEL / 128, M_TOT / 128);
        gemm_f16_async<<<grid, 256, GEMM_SMEM>>>(o16_ptr, wo16_ptr, out,
                                                 M_TOT, DMODEL, DMODEL, 0);
    }
}

// round 12
// speedup vs baseline: 1.5225x; 1.1593x over previous
#include <cuda_runtime.h>
#include <cuda_fp16.h>
#include <cstdint>

#define NB      2
#define H       48
#define W       48
#define HW      (H * W)          // 2304
#define DMODEL  768
#define DHEAD   64
#define NHEADS  12
#define M_TOT   (NB * HW)        // 4608
#define QKV_N   (3 * DMODEL)     // 2304

__device__ __half g_qkv16[(size_t)M_TOT * QKV_N]; // fp16: q|k|v
__device__ __half g_o16[(size_t)M_TOT * DMODEL];  // attention output, fp16
__device__ __half g_x16[(size_t)M_TOT * DMODEL];  // x, fp16
__device__ __half g_wq16[(size_t)QKV_N * DMODEL]; // w_qkv, fp16
__device__ __half g_wo16[(size_t)DMODEL * DMODEL];// w_out, fp16

__device__ __forceinline__ uint32_t h2_bits(__half2 h) {
    return *reinterpret_cast<uint32_t*>(&h);
}
__device__ __forceinline__ __half2 bits_h2(uint32_t u) {
    return *reinterpret_cast<__half2*>(&u);
}

__device__ __forceinline__ void mma_f16(
    float& d0, float& d1, float& d2, float& d3,
    uint32_t a0, uint32_t a1, uint32_t a2, uint32_t a3,
    uint32_t b0, uint32_t b1)
{
    asm volatile(
        "mma.sync.aligned.m16n8k16.row.col.f32.f16.f16.f32 "
        "{%0,%1,%2,%3}, {%4,%5,%6,%7}, {%8,%9}, {%0,%1,%2,%3};"
        : "+f"(d0), "+f"(d1), "+f"(d2), "+f"(d3)
        : "r"(a0), "r"(a1), "r"(a2), "r"(a3), "r"(b0), "r"(b1));
}

__device__ __forceinline__ void ldsm4(
    uint32_t& r0, uint32_t& r1, uint32_t& r2, uint32_t& r3, uint32_t saddr)
{
    asm volatile("ldmatrix.sync.aligned.m8n8.x4.shared.b16 {%0,%1,%2,%3}, [%4];"
                 : "=r"(r0), "=r"(r1), "=r"(r2), "=r"(r3) : "r"(saddr));
}
__device__ __forceinline__ void ldsm4t(
    uint32_t& r0, uint32_t& r1, uint32_t& r2, uint32_t& r3, uint32_t saddr)
{
    asm volatile("ldmatrix.sync.aligned.m8n8.x4.trans.shared.b16 {%0,%1,%2,%3}, [%4];"
                 : "=r"(r0), "=r"(r1), "=r"(r2), "=r"(r3) : "r"(saddr));
}

__device__ __forceinline__ void cp16(uint32_t saddr, const void* g) {
    asm volatile("cp.async.cg.shared.global [%0], [%1], 16;"
                 :: "r"(saddr), "l"(g));
}
__device__ __forceinline__ uint32_t s2u(const void* p) {
    return (uint32_t)__cvta_generic_to_shared(p);
}

// ---------------------------------------------------------------------------
// Elementwise fp32 -> fp16 pre-convert.
// ---------------------------------------------------------------------------
__global__ void cvt16_kernel(const float* __restrict__ src,
                             __half* __restrict__ dst, int n4)
{
    int i = blockIdx.x * blockDim.x + threadIdx.x;
    const int stride = gridDim.x * blockDim.x;
    for (; i < n4; i += stride) {
        float4 v = ((const float4*)src)[i];
        uint2 o;
        o.x = h2_bits(__floats2half2_rn(v.x, v.y));
        o.y = h2_bits(__floats2half2_rn(v.z, v.w));
        ((uint2*)dst)[i] = o;
    }
}

// ---------------------------------------------------------------------------
// FP16 GEMM (NT) v2: BK=32, ldmatrix fragment loads, 2-stage cp.async.
// BM=BN=128, 256 threads, 8 warps (4x2), warp tile 32x64.
// smem rows: 32 halves + 8 pad = 80 B stride (GLD2=20 words) — ldmatrix
// phase banks 20i mod 32 all distinct -> conflict-free.
// Dynamic smem: 2 stages x 2 matrices x 128 x 20 words = 40960 B.
// ---------------------------------------------------------------------------
#define GLD2 20
#define GRB  80
#define GSW  (128 * GLD2)   // words per stage per matrix

__global__ __launch_bounds__(256) void gemm_f16_async(
    const __half* __restrict__ A, const __half* __restrict__ B,
    void* __restrict__ Cv, int M, int N, int K, int out_half)
{
    extern __shared__ uint32_t sm[];
    uint32_t* Asm = sm;             // [2][128][GLD2]
    uint32_t* Bsm = sm + 2 * GSW;

    const int tid  = threadIdx.x;
    const int lane = tid & 31;
    const int warp = tid >> 5;
    const int wm = (warp & 3) * 32;
    const int wn = (warp >> 2) * 64;
    const int rowBase = blockIdx.y * 128;
    const int colBase = blockIdx.x * 128;
    const int r = lane >> 2;
    const int q = lane & 3;

    // ldmatrix per-lane offset within a 16-row x 16-half block
    const uint32_t lmoff = (uint32_t)((lane & 15) * GRB + (lane >> 4) * 16);

    float acc[2][8][4];
    #pragma unroll
    for (int i = 0; i < 2; i++)
        #pragma unroll
        for (int jn = 0; jn < 8; jn++)
            #pragma unroll
            for (int t = 0; t < 4; t++)
                acc[i][jn][t] = 0.0f;

    // Copy mapping: 512 16B chunks per matrix per stage; 2 per thread.
    // chunk c: row = c>>2, ch = c&3 (4 x 16B per 64B row).
    const int row0 = tid >> 2, ch0 = tid & 3;
    const int row1 = row0 + 64;          // chunk tid+256
    const __half* Ap0 = A + (size_t)(rowBase + row0) * K + ch0 * 8;
    const __half* Ap1 = A + (size_t)(rowBase + row1) * K + ch0 * 8;
    const __half* Bp0 = B + (size_t)(colBase + row0) * K + ch0 * 8;
    const __half* Bp1 = B + (size_t)(colBase + row1) * K + ch0 * 8;

    uint32_t sA0[2], sA1[2], sB0[2], sB1[2];
    #pragma unroll
    for (int s = 0; s < 2; s++) {
        sA0[s] = s2u(&Asm[s * GSW + row0 * GLD2 + ch0 * 4]);
        sA1[s] = s2u(&Asm[s * GSW + row1 * GLD2 + ch0 * 4]);
        sB0[s] = s2u(&Bsm[s * GSW + row0 * GLD2 + ch0 * 4]);
        sB1[s] = s2u(&Bsm[s * GSW + row1 * GLD2 + ch0 * 4]);
    }

    // Prologue: tile 0 -> stage 0
    cp16(sA0[0], Ap0); cp16(sA1[0], Ap1);
    cp16(sB0[0], Bp0); cp16(sB1[0], Bp1);
    asm volatile("cp.async.commit_group;");

    const int T = K / 32;
    for (int t = 0; t < T; t++) {
        const int cur = t & 1;
        const int nxt = cur ^ 1;
        const bool more = (t + 1 < T);
        if (more) {
            const int k0 = (t + 1) * 32;
            cp16(sA0[nxt], Ap0 + k0); cp16(sA1[nxt], Ap1 + k0);
            cp16(sB0[nxt], Bp0 + k0); cp16(sB1[nxt], Bp1 + k0);
            asm volatile("cp.async.commit_group;");
            asm volatile("cp.async.wait_group 1;");
        } else {
            asm volatile("cp.async.wait_group 0;");
        }
        __syncthreads();

        const uint32_t Abase = s2u(Asm) + cur * (GSW * 4);
        const uint32_t Bbase = s2u(Bsm) + cur * (GSW * 4);

        #pragma unroll
        for (int kb = 0; kb < 2; kb++) {   // two 16-half k-blocks
            uint32_t af0[4], af1[4];
            ldsm4(af0[0], af0[1], af0[2], af0[3],
                  Abase + (uint32_t)((wm)      * GRB + kb * 32) + lmoff);
            ldsm4(af1[0], af1[1], af1[2], af1[3],
                  Abase + (uint32_t)((wm + 16) * GRB + kb * 32) + lmoff);
            #pragma unroll
            for (int p = 0; p < 4; p++) {  // four 16-col n-blocks
                uint32_t b0a, b0b, b1a, b1b;
                ldsm4(b0a, b0b, b1a, b1b,
                      Bbase + (uint32_t)((wn + p * 16) * GRB + kb * 32) + lmoff);
                mma_f16(acc[0][2*p][0],   acc[0][2*p][1],   acc[0][2*p][2],   acc[0][2*p][3],
                        af0[0], af0[1], af0[2], af0[3], b0a, b1a);
                mma_f16(acc[0][2*p+1][0], acc[0][2*p+1][1], acc[0][2*p+1][2], acc[0][2*p+1][3],
                        af0[0], af0[1], af0[2], af0[3], b0b, b1b);
                mma_f16(acc[1][2*p][0],   acc[1][2*p][1],   acc[1][2*p][2],   acc[1][2*p][3],
                        af1[0], af1[1], af1[2], af1[3], b0a, b1a);
                mma_f16(acc[1][2*p+1][0], acc[1][2*p+1][1], acc[1][2*p+1][2], acc[1][2*p+1][3],
                        af1[0], af1[1], af1[2], af1[3], b0b, b1b);
            }
        }
        __syncthreads();
    }

    #pragma unroll
    for (int i = 0; i < 2; i++) {
        #pragma unroll
        for (int jn = 0; jn < 8; jn++) {
            const int row = rowBase + wm + i * 16 + r;
            const int col = colBase + wn + jn * 8 + q * 2;
            if (out_half) {
                __half* Ch = (__half*)Cv;
                *(uint32_t*)(Ch + (size_t)row * N + col) =
                    h2_bits(__floats2half2_rn(acc[i][jn][0], acc[i][jn][1]));
                *(uint32_t*)(Ch + (size_t)(row + 8) * N + col) =
                    h2_bits(__floats2half2_rn(acc[i][jn][2], acc[i][jn][3]));
            } else {
                float* Cf = (float*)Cv;
                *(float2*)(Cf + (size_t)row * N + col) =
                    make_float2(acc[i][jn][0], acc[i][jn][1]);
                *(float2*)(Cf + (size_t)(row + 8) * N + col) =
                    make_float2(acc[i][jn][2], acc[i][jn][3]);
            }
        }
    }
}

// ---------------------------------------------------------------------------
// FP16 tensor-core neighborhood attention (R11 design — validated; unchanged).
// ---------------------------------------------------------------------------
#define RLD 36   // words per row (64 halves + 8 pad)
#define RB  144  // bytes per row
#define TWORDS (48 * RLD)

__global__ __launch_bounds__(96) void natten_mma(const int* __restrict__ ks_ptr)
{
    __shared__ __align__(16) uint32_t Qs[TWORDS];
    __shared__ __align__(16) uint32_t Kb[3][TWORDS];
    __shared__ __align__(16) uint32_t Vb[3][TWORDS];

    const int ks   = *ks_ptr;
    const int tid  = threadIdx.x;
    const int lane = tid & 31;
    const int warp = tid >> 5;
    const int qx   = blockIdx.x;
    const int head = blockIdx.y;
    const int b    = blockIdx.z;

    const int r = lane >> 2;
    const int j = lane & 3;
    const int grow = warp * 16 + r;

    const uint32_t lmoff = (uint32_t)((lane & 15) * RB + (lane >> 4) * 16);

    const __half* qbase = g_qkv16 + (size_t)(b * HW + qx * W) * QKV_N + head * DHEAD;
    const __half2 hscale = __float2half2_rn(0.125f);
    for (int i = tid; i < 48 * 8; i += 96) {
        const int row = i >> 3, ch = i & 7;
        uint4 v = *(const uint4*)(qbase + (size_t)row * QKV_N + ch * 8);
        v.x = h2_bits(__hmul2(bits_h2(v.x), hscale));
        v.y = h2_bits(__hmul2(bits_h2(v.y), hscale));
        v.z = h2_bits(__hmul2(bits_h2(v.z), hscale));
        v.w = h2_bits(__hmul2(bits_h2(v.w), hscale));
        *(uint4*)&Qs[row * RLD + ch * 4] = v;
    }

    const int x0 = max(0, qx - ks), x1 = min(H - 1, qx + ks);
    const int nkx = x1 - x0 + 1;

    const __half* kvbase = g_qkv16 + (size_t)(b * HW) * QKV_N + DMODEL + head * DHEAD;

    uint32_t kS[3], vS[3];
    #pragma unroll
    for (int s = 0; s < 3; s++) {
        kS[s] = s2u(&Kb[s][0]);
        vS[s] = s2u(&Vb[s][0]);
    }

    auto fill = [&](int buf, int kx) {
        const __half* krow = kvbase + (size_t)(kx * W) * QKV_N;
        const __half* vrow = krow + DMODEL;
        #pragma unroll
        for (int c = 0; c < 4; c++) {
            const int chunk = tid + c * 96;
            const int row = chunk >> 3, ch = chunk & 7;
            const size_t goff = (size_t)row * QKV_N + ch * 8;
            const uint32_t soff = (uint32_t)(row * RB + ch * 16);
            cp16(kS[buf] + soff, krow + goff);
            cp16(vS[buf] + soff, vrow + goff);
        }
    };

    fill(0, x0);
    asm volatile("cp.async.commit_group;");
    if (nkx > 1) fill(1, x0 + 1);
    asm volatile("cp.async.commit_group;");

    float o[8][4];
    #pragma unroll
    for (int nt = 0; nt < 8; nt++)
        #pragma unroll
        for (int t = 0; t < 4; t++)
            o[nt][t] = 0.0f;
    float m0 = -1e30f, m1 = -1e30f, l0 = 0.0f, l1 = 0.0f;

    uint32_t qf[4][4];
    bool qf_loaded = false;

    for (int t = 0; t < nkx; t++) {
        asm volatile("cp.async.wait_group 1;");
        __syncthreads();

        if (!qf_loaded) {
            const uint32_t qa = s2u(Qs) + (uint32_t)(warp * 16 * RB) + lmoff;
            #pragma unroll
            for (int kk = 0; kk < 4; kk++)
                ldsm4(qf[kk][0], qf[kk][1], qf[kk][2], qf[kk][3], qa + kk * 32);
            qf_loaded = true;
        }

        if (t + 2 < nkx) fill((t + 2) % 3, x0 + t + 2);
        asm volatile("cp.async.commit_group;");

        const int buf = t % 3;

        float sc[6][4];
        #pragma unroll
        for (int nt = 0; nt < 6; nt++)
            #pragma unroll
            for (int tt = 0; tt < 4; tt++)
                sc[nt][tt] = 0.0f;

        #pragma unroll
        for (int p = 0; p < 3; p++) {
            const uint32_t ka = kS[buf] + (uint32_t)(16 * p * RB) + lmoff;
            #pragma unroll
            for (int kk = 0; kk < 4; kk++) {
                uint32_t b0a, b0b, b1a, b1b;
                ldsm4(b0a, b0b, b1a, b1b, ka + kk * 32);
                mma_f16(sc[2*p][0], sc[2*p][1], sc[2*p][2], sc[2*p][3],
                        qf[kk][0], qf[kk][1], qf[kk][2], qf[kk][3], b0a, b1a);
                mma_f16(sc[2*p+1][0], sc[2*p+1][1], sc[2*p+1][2], sc[2*p+1][3],
                        qf[kk][0], qf[kk][1], qf[kk][2], qf[kk][3], b0b, b1b);
            }
        }

        float rmax0 = -1e30f, rmax1 = -1e30f;
        #pragma unroll
        for (int nt = 0; nt < 6; nt++) {
            const int ky0 = nt * 8 + 2 * j;
            const int ky1 = ky0 + 1;
            if (abs(grow - ky0) > ks)     sc[nt][0] = -1e30f;
            if (abs(grow - ky1) > ks)     sc[nt][1] = -1e30f;
            if (abs(grow + 8 - ky0) > ks) sc[nt][2] = -1e30f;
            if (abs(grow + 8 - ky1) > ks) sc[nt][3] = -1e30f;
            rmax0 = fmaxf(rmax0, fmaxf(sc[nt][0], sc[nt][1]));
            rmax1 = fmaxf(rmax1, fmaxf(sc[nt][2], sc[nt][3]));
        }
        rmax0 = fmaxf(rmax0, __shfl_xor_sync(0xffffffffu, rmax0, 1));
        rmax0 = fmaxf(rmax0, __shfl_xor_sync(0xffffffffu, rmax0, 2));
        rmax1 = fmaxf(rmax1, __shfl_xor_sync(0xffffffffu, rmax1, 1));
        rmax1 = fmaxf(rmax1, __shfl_xor_sync(0xffffffffu, rmax1, 2));

        const float mn0 = fmaxf(m0, rmax0);
        const float mn1 = fmaxf(m1, rmax1);
        const float cr0 = __expf(m0 - mn0);
        const float cr1 = __expf(m1 - mn1);
        m0 = mn0; m1 = mn1;

        float ps0 = 0.0f, ps1 = 0.0f;
        #pragma unroll
        for (int nt = 0; nt < 6; nt++) {
            sc[nt][0] = __expf(sc[nt][0] - mn0);
            sc[nt][1] = __expf(sc[nt][1] - mn0);
            sc[nt][2] = __expf(sc[nt][2] - mn1);
            sc[nt][3] = __expf(sc[nt][3] - mn1);
            ps0 += sc[nt][0] + sc[nt][1];
            ps1 += sc[nt][2] + sc[nt][3];
        }
        ps0 += __shfl_xor_sync(0xffffffffu, ps0, 1);
        ps0 += __shfl_xor_sync(0xffffffffu, ps0, 2);
        ps1 += __shfl_xor_sync(0xffffffffu, ps1, 1);
        ps1 += __shfl_xor_sync(0xffffffffu, ps1, 2);
        l0 = l0 * cr0 + ps0;
        l1 = l1 * cr1 + ps1;

        #pragma unroll
        for (int nt = 0; nt < 8; nt++) {
            o[nt][0] *= cr0; o[nt][1] *= cr0;
            o[nt][2] *= cr1; o[nt][3] *= cr1;
        }

        #pragma unroll
        for (int kk = 0; kk < 3; kk++) {
            const uint32_t pa0 = h2_bits(__floats2half2_rn(sc[2*kk][0],   sc[2*kk][1]));
            const uint32_t pa1 = h2_bits(__floats2half2_rn(sc[2*kk][2],   sc[2*kk][3]));
            const uint32_t pa2 = h2_bits(__floats2half2_rn(sc[2*kk+1][0], sc[2*kk+1][1]));
            const uint32_t pa3 = h2_bits(__floats2half2_rn(sc[2*kk+1][2], sc[2*kk+1][3]));
            const uint32_t va = vS[buf] + (uint32_t)(16 * kk * RB) + lmoff;
            #pragma unroll
            for (int p = 0; p < 4; p++) {
                uint32_t b0a, b1a, b0b, b1b;
                ldsm4t(b0a, b1a, b0b, b1b, va + p * 32);
                mma_f16(o[2*p][0], o[2*p][1], o[2*p][2], o[2*p][3],
                        pa0, pa1, pa2, pa3, b0a, b1a);
                mma_f16(o[2*p+1][0], o[2*p+1][1], o[2*p+1][2], o[2*p+1][3],
                        pa0, pa1, pa2, pa3, b0b, b1b);
            }
        }
    }

    const float inv0 = 1.0f / l0;
    const float inv1 = 1.0f / l1;
    __half* ob0 = g_o16 + (size_t)(b * HW + qx * W + grow)     * DMODEL + head * DHEAD;
    __half* ob1 = g_o16 + (size_t)(b * HW + qx * W + grow + 8) * DMODEL + head * DHEAD;
    #pragma unroll
    for (int nt = 0; nt < 8; nt++) {
        const int col = nt * 8 + 2 * j;
        *(uint32_t*)(ob0 + col) =
            h2_bits(__floats2half2_rn(o[nt][0] * inv0, o[nt][1] * inv0));
        *(uint32_t*)(ob1 + col) =
            h2_bits(__floats2half2_rn(o[nt][2] * inv1, o[nt][3] * inv1));
    }
}

// ---------------------------------------------------------------------------
extern "C" void kernel_launch(void* const* d_in, const int* in_sizes, int n_in,
                              void* d_out, int out_size)
{
    const float* x      = (const float*)d_in[0];
    const float* w_qkv  = (const float*)d_in[1];
    const float* w_out  = (const float*)d_in[2];
    const int*   ksp    = (const int*)  d_in[3];
    float*       out    = (float*)d_out;

    __half *qkv16_ptr, *o16_ptr, *x16_ptr, *wq16_ptr, *wo16_ptr;
    cudaGetSymbolAddress((void**)&qkv16_ptr, g_qkv16);
    cudaGetSymbolAddress((void**)&o16_ptr,   g_o16);
    cudaGetSymbolAddress((void**)&x16_ptr,   g_x16);
    cudaGetSymbolAddress((void**)&wq16_ptr,  g_wq16);
    cudaGetSymbolAddress((void**)&wo16_ptr,  g_wo16);

    const int GEMM_SMEM = 4 * GSW * 4;   // 40960 B
    static int attr_set = 0;
    if (!attr_set) {
        cudaFuncSetAttribute(gemm_f16_async,
                             cudaFuncAttributeMaxDynamicSharedMemorySize, GEMM_SMEM);
        attr_set = 1;
    }

    // 0) fp16 pre-conversion of inputs
    cvt16_kernel<<<512, 256>>>(x,     x16_ptr,  M_TOT * DMODEL / 4);
    cvt16_kernel<<<512, 256>>>(w_qkv, wq16_ptr, QKV_N * DMODEL / 4);
    cvt16_kernel<<<256, 256>>>(w_out, wo16_ptr, DMODEL * DMODEL / 4);

    // 1) QKV projection (fp16 in, fp16 out)
    {
        dim3 grid(QKV_N / 128, M_TOT / 128);
        gemm_f16_async<<<grid, 256, GEMM_SMEM>>>(x16_ptr, wq16_ptr, qkv16_ptr,
                                                 M_TOT, QKV_N, DMODEL, 1);
    }

    // 2) FP16 tensor-core neighborhood attention
    {
        dim3 grid(H, NHEADS, NB);
        natten_mma<<<grid, 96>>>(ksp);
    }

    // 3) Output projection (fp16 in, fp32 out)
    {
        dim3 grid(DMODEL / 128, M_TOT / 128);
        gemm_f16_async<<<grid, 256, GEMM_SMEM>>>(o16_ptr, wo16_ptr, out,
                                                 M_TOT, DMODEL, DMODEL, 0);
    }
}

// round 13
// speedup vs baseline: 1.6343x; 1.0734x over previous
#include <cuda_runtime.h>
#include <cuda_fp16.h>
#include <cstdint>

#define NB      2
#define H       48
#define W       48
#define HW      (H * W)          // 2304
#define DMODEL  768
#define DHEAD   64
#define NHEADS  12
#define M_TOT   (NB * HW)        // 4608
#define QKV_N   (3 * DMODEL)     // 2304

__device__ __half g_qkv16[(size_t)M_TOT * QKV_N]; // fp16: q|k|v
__device__ __half g_o16[(size_t)M_TOT * DMODEL];  // attention output, fp16
__device__ __half g_x16[(size_t)M_TOT * DMODEL];  // x, fp16
__device__ __half g_wq16[(size_t)QKV_N * DMODEL]; // w_qkv, fp16
__device__ __half g_wo16[(size_t)DMODEL * DMODEL];// w_out, fp16

__device__ __forceinline__ uint32_t h2_bits(__half2 h) {
    return *reinterpret_cast<uint32_t*>(&h);
}
__device__ __forceinline__ __half2 bits_h2(uint32_t u) {
    return *reinterpret_cast<__half2*>(&u);
}

__device__ __forceinline__ void mma_f16(
    float& d0, float& d1, float& d2, float& d3,
    uint32_t a0, uint32_t a1, uint32_t a2, uint32_t a3,
    uint32_t b0, uint32_t b1)
{
    asm volatile(
        "mma.sync.aligned.m16n8k16.row.col.f32.f16.f16.f32 "
        "{%0,%1,%2,%3}, {%4,%5,%6,%7}, {%8,%9}, {%0,%1,%2,%3};"
        : "+f"(d0), "+f"(d1), "+f"(d2), "+f"(d3)
        : "r"(a0), "r"(a1), "r"(a2), "r"(a3), "r"(b0), "r"(b1));
}

__device__ __forceinline__ void ldsm4(
    uint32_t& r0, uint32_t& r1, uint32_t& r2, uint32_t& r3, uint32_t saddr)
{
    asm volatile("ldmatrix.sync.aligned.m8n8.x4.shared.b16 {%0,%1,%2,%3}, [%4];"
                 : "=r"(r0), "=r"(r1), "=r"(r2), "=r"(r3) : "r"(saddr));
}
__device__ __forceinline__ void ldsm4t(
    uint32_t& r0, uint32_t& r1, uint32_t& r2, uint32_t& r3, uint32_t saddr)
{
    asm volatile("ldmatrix.sync.aligned.m8n8.x4.trans.shared.b16 {%0,%1,%2,%3}, [%4];"
                 : "=r"(r0), "=r"(r1), "=r"(r2), "=r"(r3) : "r"(saddr));
}

__device__ __forceinline__ void cp16(uint32_t saddr, const void* g) {
    asm volatile("cp.async.cg.shared.global [%0], [%1], 16;"
                 :: "r"(saddr), "l"(g));
}
__device__ __forceinline__ uint32_t s2u(const void* p) {
    return (uint32_t)__cvta_generic_to_shared(p);
}

// ---------------------------------------------------------------------------
// Elementwise fp32 -> fp16 pre-convert.
// ---------------------------------------------------------------------------
__global__ void cvt16_kernel(const float* __restrict__ src,
                             __half* __restrict__ dst, int n4)
{
    int i = blockIdx.x * blockDim.x + threadIdx.x;
    const int stride = gridDim.x * blockDim.x;
    for (; i < n4; i += stride) {
        float4 v = ((const float4*)src)[i];
        uint2 o;
        o.x = h2_bits(__floats2half2_rn(v.x, v.y));
        o.y = h2_bits(__floats2half2_rn(v.z, v.w));
        ((uint2*)dst)[i] = o;
    }
}

// ---------------------------------------------------------------------------
// FP16 GEMM (NT) v3: BK=64, ldmatrix fragments, 2-stage cp.async,
// ONE __syncthreads per k-tile (12 total for K=768).
// BM=BN=128, 256 threads, 8 warps (4x2), warp tile 32x64.
// smem rows: 64 halves + 8 pad = 144 B stride — ldmatrix row-banks 4i mod 32,
// conflict-free (same layout validated in the attention kernel).
// Dynamic smem: 2 stages x 2 matrices x 128 rows x 144 B = 73728 B.
// Pipeline body: wait_group 0 -> sync -> issue copies for tile t+1 -> compute.
//   safety: buffer nxt was last read at iter t-1; every warp passed this
//   iteration's sync only after finishing t-1's compute.
// ---------------------------------------------------------------------------
#define GLD2 36              // words per row (64 halves + 8 pad)
#define GRB  144             // bytes per row
#define GSW  (128 * GLD2)    // words per stage per matrix

__global__ __launch_bounds__(256) void gemm_f16_async(
    const __half* __restrict__ A, const __half* __restrict__ B,
    void* __restrict__ Cv, int M, int N, int K, int out_half)
{
    extern __shared__ uint32_t sm[];
    uint32_t* Asm = sm;             // [2][128][GLD2]
    uint32_t* Bsm = sm + 2 * GSW;

    const int tid  = threadIdx.x;
    const int lane = tid & 31;
    const int warp = tid >> 5;
    const int wm = (warp & 3) * 32;
    const int wn = (warp >> 2) * 64;
    const int rowBase = blockIdx.y * 128;
    const int colBase = blockIdx.x * 128;
    const int r = lane >> 2;
    const int q = lane & 3;

    // ldmatrix per-lane offset within a 16-row block
    const uint32_t lmoff = (uint32_t)((lane & 15) * GRB + (lane >> 4) * 16);

    float acc[2][8][4];
    #pragma unroll
    for (int i = 0; i < 2; i++)
        #pragma unroll
        for (int jn = 0; jn < 8; jn++)
            #pragma unroll
            for (int t = 0; t < 4; t++)
                acc[i][jn][t] = 0.0f;

    // Copy mapping: 1024 16B chunks per matrix per stage (128 rows x 8);
    // 256 threads -> 4 chunks per thread per matrix.
    const int row0 = tid >> 3, ch0 = tid & 7;      // chunk = tid + c*256
    const __half* Ap = A + (size_t)(rowBase + row0) * K + ch0 * 8;
    const __half* Bp = B + (size_t)(colBase + row0) * K + ch0 * 8;

    const uint32_t sAb = s2u(Asm) + (uint32_t)(row0 * GRB + ch0 * 16);
    const uint32_t sBb = s2u(Bsm) + (uint32_t)(row0 * GRB + ch0 * 16);

    // copy tile (k0) into stage s: rows row0 + 32*c
    auto copyTile = [&](int s, int k0) {
        #pragma unroll
        for (int c = 0; c < 4; c++) {
            const uint32_t soff = (uint32_t)(s * GSW * 4 + c * 32 * GRB);
            const size_t goff = (size_t)(c * 32) * K + k0;
            cp16(sAb + soff, Ap + goff);
            cp16(sBb + soff, Bp + goff);
        }
    };

    // Prologue: tile 0 -> stage 0
    copyTile(0, 0);
    asm volatile("cp.async.commit_group;");

    const int T = K / 64;   // 12
    for (int t = 0; t < T; t++) {
        const int cur = t & 1;
        const int nxt = cur ^ 1;

        asm volatile("cp.async.wait_group 0;");
        __syncthreads();

        if (t + 1 < T) {
            copyTile(nxt, (t + 1) * 64);
            asm volatile("cp.async.commit_group;");
        }

        const uint32_t Abase = s2u(Asm) + cur * (GSW * 4);
        const uint32_t Bbase = s2u(Bsm) + cur * (GSW * 4);

        #pragma unroll
        for (int kb = 0; kb < 4; kb++) {   // four 16-half k-blocks
            uint32_t af0[4], af1[4];
            ldsm4(af0[0], af0[1], af0[2], af0[3],
                  Abase + (uint32_t)((wm)      * GRB + kb * 32) + lmoff);
            ldsm4(af1[0], af1[1], af1[2], af1[3],
                  Abase + (uint32_t)((wm + 16) * GRB + kb * 32) + lmoff);
            #pragma unroll
            for (int p = 0; p < 4; p++) {  // four 16-col n-blocks
                uint32_t b0a, b0b, b1a, b1b;
                ldsm4(b0a, b0b, b1a, b1b,
                      Bbase + (uint32_t)((wn + p * 16) * GRB + kb * 32) + lmoff);
                mma_f16(acc[0][2*p][0],   acc[0][2*p][1],   acc[0][2*p][2],   acc[0][2*p][3],
                        af0[0], af0[1], af0[2], af0[3], b0a, b1a);
                mma_f16(acc[0][2*p+1][0], acc[0][2*p+1][1], acc[0][2*p+1][2], acc[0][2*p+1][3],
                        af0[0], af0[1], af0[2], af0[3], b0b, b1b);
                mma_f16(acc[1][2*p][0],   acc[1][2*p][1],   acc[1][2*p][2],   acc[1][2*p][3],
                        af1[0], af1[1], af1[2], af1[3], b0a, b1a);
                mma_f16(acc[1][2*p+1][0], acc[1][2*p+1][1], acc[1][2*p+1][2], acc[1][2*p+1][3],
                        af1[0], af1[1], af1[2], af1[3], b0b, b1b);
            }
        }
    }

    #pragma unroll
    for (int i = 0; i < 2; i++) {
        #pragma unroll
        for (int jn = 0; jn < 8; jn++) {
            const int row = rowBase + wm + i * 16 + r;
            const int col = colBase + wn + jn * 8 + q * 2;
            if (out_half) {
                __half* Ch = (__half*)Cv;
                *(uint32_t*)(Ch + (size_t)row * N + col) =
                    h2_bits(__floats2half2_rn(acc[i][jn][0], acc[i][jn][1]));
                *(uint32_t*)(Ch + (size_t)(row + 8) * N + col) =
                    h2_bits(__floats2half2_rn(acc[i][jn][2], acc[i][jn][3]));
            } else {
                float* Cf = (float*)Cv;
                *(float2*)(Cf + (size_t)row * N + col) =
                    make_float2(acc[i][jn][0], acc[i][jn][1]);
                *(float2*)(Cf + (size_t)(row + 8) * N + col) =
                    make_float2(acc[i][jn][2], acc[i][jn][3]);
            }
        }
    }
}

// ---------------------------------------------------------------------------
// FP16 tensor-core neighborhood attention (R11/R12 design — unchanged).
// ---------------------------------------------------------------------------
#define RLD 36   // words per row (64 halves + 8 pad)
#define RB  144  // bytes per row
#define TWORDS (48 * RLD)

__global__ __launch_bounds__(96) void natten_mma(const int* __restrict__ ks_ptr)
{
    __shared__ __align__(16) uint32_t Qs[TWORDS];
    __shared__ __align__(16) uint32_t Kb[3][TWORDS];
    __shared__ __align__(16) uint32_t Vb[3][TWORDS];

    const int ks   = *ks_ptr;
    const int tid  = threadIdx.x;
    const int lane = tid & 31;
    const int warp = tid >> 5;
    const int qx   = blockIdx.x;
    const int head = blockIdx.y;
    const int b    = blockIdx.z;

    const int r = lane >> 2;
    const int j = lane & 3;
    const int grow = warp * 16 + r;

    const uint32_t lmoff = (uint32_t)((lane & 15) * RB + (lane >> 4) * 16);

    const __half* qbase = g_qkv16 + (size_t)(b * HW + qx * W) * QKV_N + head * DHEAD;
    const __half2 hscale = __float2half2_rn(0.125f);
    for (int i = tid; i < 48 * 8; i += 96) {
        const int row = i >> 3, ch = i & 7;
        uint4 v = *(const uint4*)(qbase + (size_t)row * QKV_N + ch * 8);
        v.x = h2_bits(__hmul2(bits_h2(v.x), hscale));
        v.y = h2_bits(__hmul2(bits_h2(v.y), hscale));
        v.z = h2_bits(__hmul2(bits_h2(v.z), hscale));
        v.w = h2_bits(__hmul2(bits_h2(v.w), hscale));
        *(uint4*)&Qs[row * RLD + ch * 4] = v;
    }

    const int x0 = max(0, qx - ks), x1 = min(H - 1, qx + ks);
    const int nkx = x1 - x0 + 1;

    const __half* kvbase = g_qkv16 + (size_t)(b * HW) * QKV_N + DMODEL + head * DHEAD;

    uint32_t kS[3], vS[3];
    #pragma unroll
    for (int s = 0; s < 3; s++) {
        kS[s] = s2u(&Kb[s][0]);
        vS[s] = s2u(&Vb[s][0]);
    }

    auto fill = [&](int buf, int kx) {
        const __half* krow = kvbase + (size_t)(kx * W) * QKV_N;
        const __half* vrow = krow + DMODEL;
        #pragma unroll
        for (int c = 0; c < 4; c++) {
            const int chunk = tid + c * 96;
            const int row = chunk >> 3, ch = chunk & 7;
            const size_t goff = (size_t)row * QKV_N + ch * 8;
            const uint32_t soff = (uint32_t)(row * RB + ch * 16);
            cp16(kS[buf] + soff, krow + goff);
            cp16(vS[buf] + soff, vrow + goff);
        }
    };

    fill(0, x0);
    asm volatile("cp.async.commit_group;");
    if (nkx > 1) fill(1, x0 + 1);
    asm volatile("cp.async.commit_group;");

    float o[8][4];
    #pragma unroll
    for (int nt = 0; nt < 8; nt++)
        #pragma unroll
        for (int t = 0; t < 4; t++)
            o[nt][t] = 0.0f;
    float m0 = -1e30f, m1 = -1e30f, l0 = 0.0f, l1 = 0.0f;

    uint32_t qf[4][4];
    bool qf_loaded = false;

    for (int t = 0; t < nkx; t++) {
        asm volatile("cp.async.wait_group 1;");
        __syncthreads();

        if (!qf_loaded) {
            const uint32_t qa = s2u(Qs) + (uint32_t)(warp * 16 * RB) + lmoff;
            #pragma unroll
            for (int kk = 0; kk < 4; kk++)
                ldsm4(qf[kk][0], qf[kk][1], qf[kk][2], qf[kk][3], qa + kk * 32);
            qf_loaded = true;
        }

        if (t + 2 < nkx) fill((t + 2) % 3, x0 + t + 2);
        asm volatile("cp.async.commit_group;");

        const int buf = t % 3;

        float sc[6][4];
        #pragma unroll
        for (int nt = 0; nt < 6; nt++)
            #pragma unroll
            for (int tt = 0; tt < 4; tt++)
                sc[nt][tt] = 0.0f;

        #pragma unroll
        for (int p = 0; p < 3; p++) {
            const uint32_t ka = kS[buf] + (uint32_t)(16 * p * RB) + lmoff;
            #pragma unroll
            for (int kk = 0; kk < 4; kk++) {
                uint32_t b0a, b0b, b1a, b1b;
                ldsm4(b0a, b0b, b1a, b1b, ka + kk * 32);
                mma_f16(sc[2*p][0], sc[2*p][1], sc[2*p][2], sc[2*p][3],
                        qf[kk][0], qf[kk][1], qf[kk][2], qf[kk][3], b0a, b1a);
                mma_f16(sc[2*p+1][0], sc[2*p+1][1], sc[2*p+1][2], sc[2*p+1][3],
                        qf[kk][0], qf[kk][1], qf[kk][2], qf[kk][3], b0b, b1b);
            }
        }

        float rmax0 = -1e30f, rmax1 = -1e30f;
        #pragma unroll
        for (int nt = 0; nt < 6; nt++) {
            const int ky0 = nt * 8 + 2 * j;
            const int ky1 = ky0 + 1;
            if (abs(grow - ky0) > ks)     sc[nt][0] = -1e30f;
            if (abs(grow - ky1) > ks)     sc[nt][1] = -1e30f;
            if (abs(grow + 8 - ky0) > ks) sc[nt][2] = -1e30f;
            if (abs(grow + 8 - ky1) > ks) sc[nt][3] = -1e30f;
            rmax0 = fmaxf(rmax0, fmaxf(sc[nt][0], sc[nt][1]));
            rmax1 = fmaxf(rmax1, fmaxf(sc[nt][2], sc[nt][3]));
        }
        rmax0 = fmaxf(rmax0, __shfl_xor_sync(0xffffffffu, rmax0, 1));
        rmax0 = fmaxf(rmax0, __shfl_xor_sync(0xffffffffu, rmax0, 2));
        rmax1 = fmaxf(rmax1, __shfl_xor_sync(0xffffffffu, rmax1, 1));
        rmax1 = fmaxf(rmax1, __shfl_xor_sync(0xffffffffu, rmax1, 2));

        const float mn0 = fmaxf(m0, rmax0);
        const float mn1 = fmaxf(m1, rmax1);
        const float cr0 = __expf(m0 - mn0);
        const float cr1 = __expf(m1 - mn1);
        m0 = mn0; m1 = mn1;

        float ps0 = 0.0f, ps1 = 0.0f;
        #pragma unroll
        for (int nt = 0; nt < 6; nt++) {
            sc[nt][0] = __expf(sc[nt][0] - mn0);
            sc[nt][1] = __expf(sc[nt][1] - mn0);
            sc[nt][2] = __expf(sc[nt][2] - mn1);
            sc[nt][3] = __expf(sc[nt][3] - mn1);
            ps0 += sc[nt][0] + sc[nt][1];
            ps1 += sc[nt][2] + sc[nt][3];
        }
        ps0 += __shfl_xor_sync(0xffffffffu, ps0, 1);
        ps0 += __shfl_xor_sync(0xffffffffu, ps0, 2);
        ps1 += __shfl_xor_sync(0xffffffffu, ps1, 1);
        ps1 += __shfl_xor_sync(0xffffffffu, ps1, 2);
        l0 = l0 * cr0 + ps0;
        l1 = l1 * cr1 + ps1;

        #pragma unroll
        for (int nt = 0; nt < 8; nt++) {
            o[nt][0] *= cr0; o[nt][1] *= cr0;
            o[nt][2] *= cr1; o[nt][3] *= cr1;
        }

        #pragma unroll
        for (int kk = 0; kk < 3; kk++) {
            const uint32_t pa0 = h2_bits(__floats2half2_rn(sc[2*kk][0],   sc[2*kk][1]));
            const uint32_t pa1 = h2_bits(__floats2half2_rn(sc[2*kk][2],   sc[2*kk][3]));
            const uint32_t pa2 = h2_bits(__floats2half2_rn(sc[2*kk+1][0], sc[2*kk+1][1]));
            const uint32_t pa3 = h2_bits(__floats2half2_rn(sc[2*kk+1][2], sc[2*kk+1][3]));
            const uint32_t va = vS[buf] + (uint32_t)(16 * kk * RB) + lmoff;
            #pragma unroll
            for (int p = 0; p < 4; p++) {
                uint32_t b0a, b1a, b0b, b1b;
                ldsm4t(b0a, b1a, b0b, b1b, va + p * 32);
                mma_f16(o[2*p][0], o[2*p][1], o[2*p][2], o[2*p][3],
                        pa0, pa1, pa2, pa3, b0a, b1a);
                mma_f16(o[2*p+1][0], o[2*p+1][1], o[2*p+1][2], o[2*p+1][3],
                        pa0, pa1, pa2, pa3, b0b, b1b);
            }
        }
    }

    const float inv0 = 1.0f / l0;
    const float inv1 = 1.0f / l1;
    __half* ob0 = g_o16 + (size_t)(b * HW + qx * W + grow)     * DMODEL + head * DHEAD;
    __half* ob1 = g_o16 + (size_t)(b * HW + qx * W + grow + 8) * DMODEL + head * DHEAD;
    #pragma unroll
    for (int nt = 0; nt < 8; nt++) {
        const int col = nt * 8 + 2 * j;
        *(uint32_t*)(ob0 + col) =
            h2_bits(__floats2half2_rn(o[nt][0] * inv0, o[nt][1] * inv0));
        *(uint32_t*)(ob1 + col) =
            h2_bits(__floats2half2_rn(o[nt][2] * inv1, o[nt][3] * inv1));
    }
}

// ---------------------------------------------------------------------------
extern "C" void kernel_launch(void* const* d_in, const int* in_sizes, int n_in,
                              void* d_out, int out_size)
{
    const float* x      = (const float*)d_in[0];
    const float* w_qkv  = (const float*)d_in[1];
    const float* w_out  = (const float*)d_in[2];
    const int*   ksp    = (const int*)  d_in[3];
    float*       out    = (float*)d_out;

    __half *qkv16_ptr, *o16_ptr, *x16_ptr, *wq16_ptr, *wo16_ptr;
    cudaGetSymbolAddress((void**)&qkv16_ptr, g_qkv16);
    cudaGetSymbolAddress((void**)&o16_ptr,   g_o16);
    cudaGetSymbolAddress((void**)&x16_ptr,   g_x16);
    cudaGetSymbolAddress((void**)&wq16_ptr,  g_wq16);
    cudaGetSymbolAddress((void**)&wo16_ptr,  g_wo16);

    const int GEMM_SMEM = 4 * GSW * 4;   // 73728 B
    static int attr_set = 0;
    if (!attr_set) {
        cudaFuncSetAttribute(gemm_f16_async,
                             cudaFuncAttributeMaxDynamicSharedMemorySize, GEMM_SMEM);
        attr_set = 1;
    }

    // 0) fp16 pre-conversion of inputs
    cvt16_kernel<<<512, 256>>>(x,     x16_ptr,  M_TOT * DMODEL / 4);
    cvt16_kernel<<<512, 256>>>(w_qkv, wq16_ptr, QKV_N * DMODEL / 4);
    cvt16_kernel<<<256, 256>>>(w_out, wo16_ptr, DMODEL * DMODEL / 4);

    // 1) QKV projection (fp16 in, fp16 out)
    {
        dim3 grid(QKV_N / 128, M_TOT / 128);
        gemm_f16_async<<<grid, 256, GEMM_SMEM>>>(x16_ptr, wq16_ptr, qkv16_ptr,
                                                 M_TOT, QKV_N, DMODEL, 1);
    }

    // 2) FP16 tensor-core neighborhood attention
    {
        dim3 grid(H, NHEADS, NB);
        natten_mma<<<grid, 96>>>(ksp);
    }

    // 3) Output projection (fp16 in, fp32 out)
    {
        dim3 grid(DMODEL / 128, M_TOT / 128);
        gemm_f16_async<<<grid, 256, GEMM_SMEM>>>(o16_ptr, wo16_ptr, out,
                                                 M_TOT, DMODEL, DMODEL, 0);
    }
}